// round 14
// baseline (speedup 1.0000x reference)
#include <cuda_runtime.h>
#include <cuda_fp16.h>
#include <math.h>
#include <stdint.h>

typedef unsigned long long ull;

// ---------------- problem dims ----------------
#define BT      4096
#define KTOT    5376
#define NOUT    70
#define NPADP   72

// GEMM config: KSPLIT=9, uneven chunk ranges (84 chunks -> 9/9/10 per split), grid 288 = 1 wave
#define KSPLIT   9
#define TOTCH    84
#define K16TOT   336
#define MTILES   32

// smem stage layout
#define ST_A    0
#define ST_B    16384
#define STAGE_BYTES 25600
#define DYN_SMEM (2 * STAGE_BYTES)   // 51200

// output layout
#define J2D_OFF   0
#define THETA_OFF 172032
#define BETA_OFF  368640

// chunk-range boundary for split ks
__host__ __device__ __forceinline__ int CS(int ks) { return (ks * TOTCH) / KSPLIT; }

// ---------------- scratch ----------------
__device__ float g_part[(size_t)KSPLIT * BT * NPADP];   // 10.6 MB
__device__ float g_params[(size_t)BT * NOUT];
__device__ __align__(16) uint2 g_Bh[K16TOT * 9 * 32];   // fp16 W frags
__device__ float g_Jsh[480];
__device__ float g_Jt[48];
__device__ __align__(16) float g_pd5[5][3][136];
__device__ float g_sd5[5][3][10];
__device__ float g_lbs5[5][16];
__device__ float g_tmpl5[16];

__device__ const int d_VIDX[5] = {743, 333, 443, 555, 678};
__device__ const int d_MAP[21] = {0,13,14,15, -1, 1,2,3, -2, 4,5,6, -3, 10,11,12, -4, 7,8,9, -5};

// ---------------- helpers ----------------
__device__ __forceinline__ uint32_t smem_u32(const void* p) {
    uint32_t a;
    asm("{ .reg .u64 t; cvta.to.shared.u64 t, %1; cvt.u32.u64 %0, t; }" : "=r"(a) : "l"(p));
    return a;
}
__device__ __forceinline__ void ffma2(ull &d, ull a, ull b) {
    asm("fma.rn.f32x2 %0, %1, %2, %0;" : "+l"(d) : "l"(a), "l"(b));
}
__device__ __forceinline__ void unpack2(ull v, float &lo, float &hi) {
    asm("mov.b64 {%0, %1}, %2;" : "=f"(lo), "=f"(hi) : "l"(v));
}
__device__ __forceinline__ uint32_t sw128(uint32_t off) { return off ^ ((off >> 3) & 0x70); }
__device__ __forceinline__ uint32_t pack_h2(float a, float b) {
    __half2 h = __floats2half2_rn(a, b);
    return *(uint32_t*)&h;
}
__device__ __forceinline__ void ldmatrix_x4(uint32_t* r, uint32_t addr) {
    asm volatile("ldmatrix.sync.aligned.m8n8.x4.shared.b16 {%0,%1,%2,%3}, [%4];"
                 : "=r"(r[0]), "=r"(r[1]), "=r"(r[2]), "=r"(r[3]) : "r"(addr));
}
__device__ __forceinline__ void mma16816(float* c, const uint32_t* a, uint32_t b0, uint32_t b1) {
    asm volatile("mma.sync.aligned.m16n8k16.row.col.f32.f16.f16.f32 "
                 "{%0,%1,%2,%3}, {%4,%5,%6,%7}, {%8,%9}, {%0,%1,%2,%3};"
                 : "+f"(c[0]), "+f"(c[1]), "+f"(c[2]), "+f"(c[3])
                 : "r"(a[0]), "r"(a[1]), "r"(a[2]), "r"(a[3]), "r"(b0), "r"(b1));
}

// ---------------- kernel 1: precompute (R11-proven layout) ----------------
// [0,132): J_reg warp reductions; [132,140): vertex gathers; [140,896): fp16 W frag table
__global__ void precompute_kernel(const float* __restrict__ Jreg,
                                  const float* __restrict__ shapedirs,
                                  const float* __restrict__ tmpl,
                                  const float* __restrict__ posedirs,
                                  const float* __restrict__ lbs,
                                  const float* __restrict__ W) {
    if (blockIdx.x < 132) {
        int gw   = blockIdx.x * (blockDim.x >> 5) + (threadIdx.x >> 5);
        int lane = threadIdx.x & 31;
        if (gw < 480) {
            int j = gw / 30; int rem = gw % 30; int c = rem / 10; int k = rem % 10;
            float s0 = 0.f, s1 = 0.f;
            const float* jr = Jreg + j * 778;
            const float* sd = shapedirs + c * 10 + k;
            for (int v = lane; v < 778 - 32; v += 64) {
                s0 += jr[v] * sd[v * 30];
                s1 += jr[v + 32] * sd[(v + 32) * 30];
            }
            {
                int v = lane + 768;
                if (v < 778) s0 += jr[v] * sd[v * 30];
            }
            float s = s0 + s1;
            #pragma unroll
            for (int o = 16; o; o >>= 1) s += __shfl_xor_sync(0xffffffffu, s, o);
            if (lane == 0) g_Jsh[gw] = s;
        } else if (gw < 528) {
            int t = gw - 480; int j = t / 3; int c = t % 3;
            float s = 0.0f;
            for (int v = lane; v < 778; v += 32)
                s += Jreg[j * 778 + v] * tmpl[v * 3 + c];
            #pragma unroll
            for (int o = 16; o; o >>= 1) s += __shfl_xor_sync(0xffffffffu, s, o);
            if (lane == 0) g_Jt[t] = s;
        }
    } else if (blockIdx.x < 140) {
        int tid = (blockIdx.x - 132) * blockDim.x + threadIdx.x;
        float* pdf = &g_pd5[0][0][0];
        for (int i = tid; i < 5 * 3 * 136; i += 1024) {
            int v = i / 408; int rem = i % 408; int c = rem / 136; int k = rem % 136;
            pdf[i] = (k < 135) ? posedirs[(size_t)d_VIDX[v] * 405 + c * 135 + k] : 0.0f;
        }
        float* sdf = &g_sd5[0][0][0];
        for (int i = tid; i < 150; i += 1024) {
            int v = i / 30;
            sdf[i] = shapedirs[(size_t)d_VIDX[v] * 30 + (i % 30)];
        }
        float* lbf = &g_lbs5[0][0];
        for (int i = tid; i < 80; i += 1024)
            lbf[i] = lbs[(size_t)d_VIDX[i / 16] * 16 + (i % 16)];
        if (tid < 15) g_tmpl5[tid] = tmpl[(size_t)d_VIDX[tid / 3] * 3 + (tid % 3)];
    } else {
        // fp16 B fragment table: idx = (kt*9 + j)*32 + lane
        int idx = (blockIdx.x - 140) * 128 + threadIdx.x;   // 756*128 = 96768 exact
        int lane = idx & 31;
        int grp  = idx >> 5;
        int j    = grp % 9;
        int kt   = grp / 9;
        int n    = j * 8 + (lane >> 2);
        int k0   = kt * 16 + 2 * (lane & 3);
        float b0 = 0, b1 = 0, b2 = 0, b3 = 0;
        if (n < NOUT) {
            const float* wp = W + (size_t)n * KTOT + k0;
            b0 = wp[0]; b1 = wp[1]; b2 = wp[8]; b3 = wp[9];
        }
        g_Bh[idx] = make_uint2(pack_h2(b0, b1), pack_h2(b2, b3));
    }
}

// ---------------- kernel 2: HMMA GEMM (single-pass fp16, 1-wave grid 288) ----------------
__global__ void __launch_bounds__(256, 2) gemm_kernel(const float* __restrict__ x) {
    extern __shared__ __align__(1024) char dyn[];

    int t    = threadIdx.x;
    int wid  = t >> 5;
    int lane = t & 31;
    int mt   = blockIdx.x & 31;
    int ks   = blockIdx.x >> 5;          // 0..8
    int rbase = mt * 128;
    int c0g   = CS(ks);                   // first global chunk
    int c1g   = CS(ks + 1);               // one past last
    int nch   = c1g - c0g;                // 9 or 10

    float acc[9][4];
    #pragma unroll
    for (int j = 0; j < 9; j++)
        #pragma unroll
        for (int i = 0; i < 4; i++) acc[j][i] = 0.0f;

    int row  = t >> 1;
    int half = t & 1;
    const float* xrow = x + (size_t)(rbase + row) * KTOT + c0g * 64 + half * 32;

    float4 xr[8];
    #pragma unroll
    for (int i = 0; i < 8; i++) xr[i] = *(const float4*)(xrow + i * 4);

    uint32_t dynb = smem_u32(dyn);
    uint32_t arow_off = (uint32_t)((wid * 16 + (lane & 15)) * 128 + (lane >> 4) * 16);

    for (int ch = 0; ch < nch; ch++) {
        int s = ch & 1;
        char* Ah = dyn + s * STAGE_BYTES + ST_A;
        // ---- convert x -> fp16 (SW128) ----
        #pragma unroll
        for (int jq = 0; jq < 4; jq++) {
            float va[8];
            *(float4*)&va[0] = xr[2 * jq];
            *(float4*)&va[4] = xr[2 * jq + 1];
            uint32_t H[4];
            #pragma unroll
            for (int p2 = 0; p2 < 4; p2++)
                H[p2] = pack_h2(va[2 * p2], va[2 * p2 + 1]);
            uint32_t off = sw128((uint32_t)(row * 128 + (half * 32 + 8 * jq) * 2));
            *(uint4*)(Ah + off) = make_uint4(H[0], H[1], H[2], H[3]);
        }
        // ---- copy B frag table for this chunk (4 k16 steps, 9216B) ----
        {
            size_t cbase = (size_t)((c0g + ch) * 4) * 288;   // uint2 units
            const uint4* srcH = (const uint4*)(g_Bh + cbase);
            uint4* dH = (uint4*)(dyn + s * STAGE_BYTES + ST_B);
            #pragma unroll
            for (int i = 0; i < 3; i++) {
                int idx = t + i * 256;
                if (idx < 576) dH[idx] = srcH[idx];
            }
        }
        // ---- prefetch next chunk's x ----
        if (ch + 1 < nch) {
            const float* xb = xrow + (ch + 1) * 64;
            #pragma unroll
            for (int i = 0; i < 8; i++) xr[i] = *(const float4*)(xb + i * 4);
        }
        __syncthreads();
        // ---- mma over 4 k16 steps ----
        uint32_t ahb = dynb + s * STAGE_BYTES + ST_A;
        const char* bhb = dyn + s * STAGE_BYTES + ST_B;
        #pragma unroll
        for (int s16 = 0; s16 < 4; s16++) {
            uint32_t off = arow_off + s16 * 32;
            uint32_t sw  = off ^ ((off >> 3) & 0x70);
            uint32_t ah[4];
            ldmatrix_x4(ah, ahb + sw);
            int bofs = ((s16 * 9) * 32 + lane) * 8;
            #pragma unroll
            for (int j = 0; j < 9; j++) {
                uint2 bh = *(const uint2*)(bhb + bofs + j * 256);
                mma16816(acc[j], ah, bh.x, bh.y);
            }
        }
        if (ch + 1 < nch) __syncthreads();
    }

    // ---- epilogue: write partials ----
    int r0 = rbase + wid * 16 + (lane >> 2);
    int c0 = 2 * (lane & 3);
    float* dst = g_part + ((size_t)ks * BT + r0) * NPADP + c0;
    #pragma unroll
    for (int j = 0; j < 9; j++) {
        *(float2*)(dst + 8 * j)                      = make_float2(acc[j][0], acc[j][1]);
        *(float2*)(dst + 8 * (size_t)NPADP + 8 * j)  = make_float2(acc[j][2], acc[j][3]);
    }
}

// ---------------- kernel 3: streaming reduce ----------------
__global__ void reduce_kernel(const float* __restrict__ b, float* __restrict__ out) {
    int idx = blockIdx.x * blockDim.x + threadIdx.x;
    if (idx >= BT * NOUT) return;
    int row = idx / NOUT;
    int c   = idx - row * NOUT;
    float s = b[c];
    const float* gp = g_part + (size_t)row * NPADP + c;
    #pragma unroll
    for (int ks = 0; ks < KSPLIT; ks++)
        s += gp[(size_t)ks * BT * NPADP];
    g_params[idx] = s;
    if (c < 48)       out[THETA_OFF + row * 48 + c] = s;
    else if (c < 58)  out[BETA_OFF  + row * 10 + (c - 48)] = s;
}

// ---------------- kernel 4: decoder (1 warp per frame; proven config) ----------------
#define WSZ     720
#define OFF_P   0
#define OFF_HP  72
#define OFF_R   120
#define OFF_ROD 264
#define OFF_J   400
#define OFF_G   448
#define OFF_CT  640
#define OFF_CH  688
#define OFF_MS  704

__global__ void __launch_bounds__(256) decoder_kernel(
        const float* __restrict__ comps,
        const float* __restrict__ meanh,
        float* __restrict__ out) {
    __shared__ float cshare[2032];
    __shared__ __align__(16) float sh[8 * WSZ];
    for (int i = threadIdx.x; i < 2025; i += 256) cshare[i] = comps[i];
    __syncthreads();

    int wid  = threadIdx.x >> 5;
    int lane = threadIdx.x & 31;
    int bt   = blockIdx.x * 8 + wid;

    float* S   = sh + wid * WSZ;
    float* p   = S + OFF_P;
    float* hp  = S + OFF_HP;
    float* R   = S + OFF_R;
    float* rod = S + OFF_ROD;
    float* Jj  = S + OFF_J;
    float* G   = S + OFF_G;
    float* CT  = S + OFF_CT;
    float* ch  = S + OFF_CH;
    float* ms  = S + OFF_MS;

    // 1. load params
    for (int i = lane; i < NOUT; i += 32) p[i] = g_params[(size_t)bt * NOUT + i];
    __syncwarp();

    // 2. full pose
    if (lane < 3) hp[lane] = p[lane];
    for (int i = lane; i < 45; i += 32) {
        float s0 = meanh[i], s1 = 0.0f, s2 = 0.0f;
        #pragma unroll
        for (int j = 0; j < 45; j += 3) {
            s0 += p[3 + j]     * cshare[j * 45 + i];
            s1 += p[3 + j + 1] * cshare[(j + 1) * 45 + i];
            s2 += p[3 + j + 2] * cshare[(j + 2) * 45 + i];
        }
        hp[3 + i] = s0 + s1 + s2;
    }
    __syncwarp();

    // 3. rodrigues
    if (lane < 16) {
        int j = lane;
        float rx = hp[3*j], ry = hp[3*j+1], rz = hp[3*j+2];
        float th = sqrtf(rx*rx + ry*ry + rz*rz + 1e-8f);
        float inv = 1.0f / th;
        float nx = rx*inv, ny = ry*inv, nz = rz*inv;
        float sn, cc;
        __sincosf(th, &sn, &cc);
        float oc = 1.0f - cc;
        float r0 = cc + oc*nx*nx,    r1 = oc*nx*ny - sn*nz, r2 = oc*nx*nz + sn*ny;
        float r3 = oc*nx*ny + sn*nz, r4 = cc + oc*ny*ny,    r5 = oc*ny*nz - sn*nx;
        float r6 = oc*nx*nz - sn*ny, r7 = oc*ny*nz + sn*nx, r8 = cc + oc*nz*nz;
        float* Rj = R + j * 9;
        Rj[0]=r0; Rj[1]=r1; Rj[2]=r2; Rj[3]=r3; Rj[4]=r4; Rj[5]=r5; Rj[6]=r6; Rj[7]=r7; Rj[8]=r8;
        if (j >= 1) {
            float* rd = rod + (j - 1) * 9;
            rd[0]=r0; rd[1]=r1; rd[2]=r2; rd[3]=r3; rd[4]=r4; rd[5]=r5; rd[6]=r6; rd[7]=r7; rd[8]=r8;
        } else {
            rod[135] = 0.0f;
        }
    }
    // 4. joints
    if (lane < 16) {
        int j = lane;
        #pragma unroll
        for (int c = 0; c < 3; c++) {
            float s = g_Jt[j * 3 + c];
            #pragma unroll
            for (int k = 0; k < 10; k++) s += g_Jsh[j * 30 + c * 10 + k] * p[48 + k];
            Jj[j * 3 + c] = s;
        }
    }
    __syncwarp();

    // 5. kinematic chain
    if (lane < 5) {
        float Gp[12];
        #pragma unroll
        for (int r = 0; r < 3; r++) {
            Gp[r*4+0] = R[r*3+0]; Gp[r*4+1] = R[r*3+1]; Gp[r*4+2] = R[r*3+2];
            Gp[r*4+3] = Jj[r];
        }
        if (lane == 0) {
            #pragma unroll
            for (int e = 0; e < 12; e++) G[e] = Gp[e];
        }
        int j = 3 * lane + 1;
        int parent = 0;
        #pragma unroll
        for (int s = 0; s < 3; s++, j++) {
            const float* Rc = R + j * 9;
            float d0 = Jj[j*3+0] - Jj[parent*3+0];
            float d1 = Jj[j*3+1] - Jj[parent*3+1];
            float d2 = Jj[j*3+2] - Jj[parent*3+2];
            float Gc[12];
            #pragma unroll
            for (int r = 0; r < 3; r++) {
                float a0 = Gp[r*4+0], a1 = Gp[r*4+1], a2 = Gp[r*4+2];
                Gc[r*4+0] = a0*Rc[0] + a1*Rc[3] + a2*Rc[6];
                Gc[r*4+1] = a0*Rc[1] + a1*Rc[4] + a2*Rc[7];
                Gc[r*4+2] = a0*Rc[2] + a1*Rc[5] + a2*Rc[8];
                Gc[r*4+3] = a0*d0 + a1*d1 + a2*d2 + Gp[r*4+3];
            }
            #pragma unroll
            for (int e = 0; e < 12; e++) { G[j*12+e] = Gc[e]; Gp[e] = Gc[e]; }
            parent = j;
        }
    }
    __syncwarp();

    // 6. corrected translations
    if (lane < 16) {
        int j = lane;
        #pragma unroll
        for (int r = 0; r < 3; r++) {
            float g0 = G[j*12+r*4+0], g1 = G[j*12+r*4+1], g2 = G[j*12+r*4+2];
            CT[j*3+r] = G[j*12+r*4+3] - (g0*Jj[j*3+0] + g1*Jj[j*3+1] + g2*Jj[j*3+2]);
        }
    }
    __syncwarp();

    // 7. posed positions at 5 mesh vertices
    if (lane < 15) {
        int v = lane / 3, c = lane - 3 * v;
        float s = g_tmpl5[lane];
        #pragma unroll
        for (int k = 0; k < 10; k++) s += g_sd5[v][c][k] * p[48 + k];
        ull a0 = 0ull, a1 = 0ull;
        const ull* pd = (const ull*)g_pd5[v][c];
        const ull* rr = (const ull*)rod;
        #pragma unroll
        for (int i = 0; i < 68; i += 2) {
            ffma2(a0, pd[i],     rr[i]);
            ffma2(a1, pd[i + 1], rr[i + 1]);
        }
        float l0, h0, l1, h1;
        unpack2(a0, l0, h0); unpack2(a1, l1, h1);
        ch[lane] = s + ((l0 + h0) + (l1 + h1));
    }
    __syncwarp();

    // 8. LBS
    if (lane < 15) {
        int v = lane / 3, r = lane - 3 * v;
        float T0 = 0, T1 = 0, T2 = 0, T3a = 0, T3b = 0;
        #pragma unroll
        for (int j = 0; j < 16; j++) {
            float w = g_lbs5[v][j];
            T0 += w * G[j*12+r*4+0];
            T1 += w * G[j*12+r*4+1];
            T2 += w * G[j*12+r*4+2];
            if (j & 1) T3a += w * CT[j*3+r]; else T3b += w * CT[j*3+r];
        }
        ms[lane] = T0 * ch[v*3+0] + T1 * ch[v*3+1] + T2 * ch[v*3+2] + (T3a + T3b);
    }
    __syncwarp();

    // 9. reorder + projection
    if (lane < 21) {
        int m = d_MAP[lane];
        float q0, q1, q2;
        if (m >= 0) { q0 = G[m*12+3]; q1 = G[m*12+7]; q2 = G[m*12+11]; }
        else        { int mi = -m - 1; q0 = ms[mi*3+0]; q1 = ms[mi*3+1]; q2 = ms[mi*3+2]; }
        float csv = p[69];
        #pragma unroll
        for (int col = 0; col < 2; col++) {
            float u = q0 * p[58 + col] + q1 * p[61 + col] + q2 * p[64 + col];
            out[J2D_OFF + (size_t)bt * 42 + lane * 2 + col] = csv * u + p[67 + col];
        }
    }
}

// ---------------- launcher ----------------
extern "C" void kernel_launch(void* const* d_in, const int* in_sizes, int n_in,
                              void* d_out, int out_size) {
    const float* x         = (const float*)d_in[0];
    const float* W         = (const float*)d_in[1];
    const float* b         = (const float*)d_in[2];
    const float* comps     = (const float*)d_in[3];
    const float* meanh     = (const float*)d_in[4];
    const float* tmpl      = (const float*)d_in[5];
    const float* shapedirs = (const float*)d_in[6];
    const float* posedirs  = (const float*)d_in[7];
    const float* Jreg      = (const float*)d_in[8];
    const float* lbs       = (const float*)d_in[9];
    float* out = (float*)d_out;

    cudaFuncSetAttribute(gemm_kernel, cudaFuncAttributeMaxDynamicSharedMemorySize, DYN_SMEM);

    precompute_kernel<<<896, 128>>>(Jreg, shapedirs, tmpl, posedirs, lbs, W);
    gemm_kernel<<<MTILES * KSPLIT, 256, DYN_SMEM>>>(x);
    reduce_kernel<<<(BT * NOUT + 255) / 256, 256>>>(b, out);
    decoder_kernel<<<BT / 8, 256>>>(comps, meanh, out);
}

// round 15
// speedup vs baseline: 1.1107x; 1.1107x over previous
#include <cuda_runtime.h>
#include <cuda_fp16.h>
#include <math.h>
#include <stdint.h>

typedef unsigned long long ull;

// ---------------- problem dims ----------------
#define BT      4096
#define KTOT    5376
#define NOUT    70
#define NPADP   72

// GEMM config: KSPLIT=9, uneven chunk ranges (84 chunks -> 9/9/10), grid 288 = 1 wave
#define KSPLIT   9
#define TOTCH    84
#define K16TOT   336
#define MTILES   32

// smem stage layout
#define ST_A    0
#define ST_B    16384
#define STAGE_BYTES 25600
#define DYN_SMEM (2 * STAGE_BYTES)   // 51200

// output layout
#define J2D_OFF   0
#define THETA_OFF 172032
#define BETA_OFF  368640

__host__ __device__ __forceinline__ int CS(int ks) { return (ks * TOTCH) / KSPLIT; }

// ---------------- scratch ----------------
__device__ float g_part[(size_t)KSPLIT * BT * NPADP];   // 10.6 MB
__device__ __align__(16) uint2 g_Bh[K16TOT * 9 * 32];   // fp16 W frags
__device__ float g_Jsh[480];
__device__ float g_Jt[48];
__device__ __align__(16) float g_pd5[5][3][136];
__device__ float g_sd5[5][3][10];
__device__ float g_lbs5[5][16];
__device__ float g_tmpl5[16];

__device__ const int d_VIDX[5] = {743, 333, 443, 555, 678};
__device__ const int d_MAP[21] = {0,13,14,15, -1, 1,2,3, -2, 4,5,6, -3, 10,11,12, -4, 7,8,9, -5};

// ---------------- helpers ----------------
__device__ __forceinline__ uint32_t smem_u32(const void* p) {
    uint32_t a;
    asm("{ .reg .u64 t; cvta.to.shared.u64 t, %1; cvt.u32.u64 %0, t; }" : "=r"(a) : "l"(p));
    return a;
}
__device__ __forceinline__ void ffma2(ull &d, ull a, ull b) {
    asm("fma.rn.f32x2 %0, %1, %2, %0;" : "+l"(d) : "l"(a), "l"(b));
}
__device__ __forceinline__ void unpack2(ull v, float &lo, float &hi) {
    asm("mov.b64 {%0, %1}, %2;" : "=f"(lo), "=f"(hi) : "l"(v));
}
__device__ __forceinline__ uint32_t sw128(uint32_t off) { return off ^ ((off >> 3) & 0x70); }
__device__ __forceinline__ uint32_t pack_h2(float a, float b) {
    __half2 h = __floats2half2_rn(a, b);
    return *(uint32_t*)&h;
}
__device__ __forceinline__ void ldmatrix_x4(uint32_t* r, uint32_t addr) {
    asm volatile("ldmatrix.sync.aligned.m8n8.x4.shared.b16 {%0,%1,%2,%3}, [%4];"
                 : "=r"(r[0]), "=r"(r[1]), "=r"(r[2]), "=r"(r[3]) : "r"(addr));
}
__device__ __forceinline__ void mma16816(float* c, const uint32_t* a, uint32_t b0, uint32_t b1) {
    asm volatile("mma.sync.aligned.m16n8k16.row.col.f32.f16.f16.f32 "
                 "{%0,%1,%2,%3}, {%4,%5,%6,%7}, {%8,%9}, {%0,%1,%2,%3};"
                 : "+f"(c[0]), "+f"(c[1]), "+f"(c[2]), "+f"(c[3])
                 : "r"(a[0]), "r"(a[1]), "r"(a[2]), "r"(a[3]), "r"(b0), "r"(b1));
}

// block-wide reduce of one float (128 threads)
__device__ __forceinline__ float block_reduce128(float s, float* red4) {
    int lane = threadIdx.x & 31, wid = threadIdx.x >> 5;
    #pragma unroll
    for (int o = 16; o; o >>= 1) s += __shfl_xor_sync(0xffffffffu, s, o);
    if (lane == 0) red4[wid] = s;
    __syncthreads();
    return red4[0] + red4[1] + red4[2] + red4[3];
}

// ---------------- kernel 1: precompute (one block per reduction output) ----------------
// [0,480): Jsh; [480,528): Jt; [528,536): vertex gathers; [536,1292): W frag table
__global__ void precompute_kernel(const float* __restrict__ Jreg,
                                  const float* __restrict__ shapedirs,
                                  const float* __restrict__ tmpl,
                                  const float* __restrict__ posedirs,
                                  const float* __restrict__ lbs,
                                  const float* __restrict__ W) {
    __shared__ float red4[4];
    int bid = blockIdx.x;
    int t   = threadIdx.x;
    if (bid < 480) {
        int j = bid / 30; int ck = bid % 30;
        const float* jr = Jreg + j * 778;
        const float* sd = shapedirs + ck;
        float s = 0.0f;
        #pragma unroll
        for (int i = 0; i < 7; i++) {
            int v = t + i * 128;
            if (v < 778) s += jr[v] * sd[v * 30];
        }
        float tot = block_reduce128(s, red4);
        if (t == 0) g_Jsh[bid] = tot;
    } else if (bid < 528) {
        int o = bid - 480; int j = o / 3; int c = o % 3;
        const float* jr = Jreg + j * 778;
        float s = 0.0f;
        #pragma unroll
        for (int i = 0; i < 7; i++) {
            int v = t + i * 128;
            if (v < 778) s += jr[v] * tmpl[v * 3 + c];
        }
        float tot = block_reduce128(s, red4);
        if (t == 0) g_Jt[o] = tot;
    } else if (bid < 536) {
        int tid = (bid - 528) * 128 + t;   // 0..1023
        float* pdf = &g_pd5[0][0][0];
        for (int i = tid; i < 5 * 3 * 136; i += 1024) {
            int v = i / 408; int rem = i % 408; int c = rem / 136; int k = rem % 136;
            pdf[i] = (k < 135) ? posedirs[(size_t)d_VIDX[v] * 405 + c * 135 + k] : 0.0f;
        }
        float* sdf = &g_sd5[0][0][0];
        for (int i = tid; i < 150; i += 1024) {
            int v = i / 30;
            sdf[i] = shapedirs[(size_t)d_VIDX[v] * 30 + (i % 30)];
        }
        float* lbf = &g_lbs5[0][0];
        for (int i = tid; i < 80; i += 1024)
            lbf[i] = lbs[(size_t)d_VIDX[i / 16] * 16 + (i % 16)];
        if (tid < 15) g_tmpl5[tid] = tmpl[(size_t)d_VIDX[tid / 3] * 3 + (tid % 3)];
    } else {
        // fp16 B fragment table: idx = (kt*9 + j)*32 + lane
        int idx = (bid - 536) * 128 + t;   // 756*128 = 96768 exact
        int lane = idx & 31;
        int grp  = idx >> 5;
        int j    = grp % 9;
        int kt   = grp / 9;
        int n    = j * 8 + (lane >> 2);
        int k0   = kt * 16 + 2 * (lane & 3);
        float b0 = 0, b1 = 0, b2 = 0, b3 = 0;
        if (n < NOUT) {
            const float* wp = W + (size_t)n * KTOT + k0;
            b0 = wp[0]; b1 = wp[1]; b2 = wp[8]; b3 = wp[9];
        }
        g_Bh[idx] = make_uint2(pack_h2(b0, b1), pack_h2(b2, b3));
    }
}

// ---------------- kernel 2: HMMA GEMM (single-pass fp16, 1-wave grid 288) ----------------
__global__ void __launch_bounds__(256, 2) gemm_kernel(const float* __restrict__ x) {
    extern __shared__ __align__(1024) char dyn[];

    int t    = threadIdx.x;
    int wid  = t >> 5;
    int lane = t & 31;
    int mt   = blockIdx.x & 31;
    int ks   = blockIdx.x >> 5;          // 0..8
    int rbase = mt * 128;
    int c0g   = CS(ks);
    int c1g   = CS(ks + 1);
    int nch   = c1g - c0g;               // 9 or 10

    float acc[9][4];
    #pragma unroll
    for (int j = 0; j < 9; j++)
        #pragma unroll
        for (int i = 0; i < 4; i++) acc[j][i] = 0.0f;

    int row  = t >> 1;
    int half = t & 1;
    const float* xrow = x + (size_t)(rbase + row) * KTOT + c0g * 64 + half * 32;

    float4 xr[8];
    #pragma unroll
    for (int i = 0; i < 8; i++) xr[i] = *(const float4*)(xrow + i * 4);

    uint32_t dynb = smem_u32(dyn);
    uint32_t arow_off = (uint32_t)((wid * 16 + (lane & 15)) * 128 + (lane >> 4) * 16);

    for (int ch = 0; ch < nch; ch++) {
        int s = ch & 1;
        char* Ah = dyn + s * STAGE_BYTES + ST_A;
        // ---- convert x -> fp16 (SW128) ----
        #pragma unroll
        for (int jq = 0; jq < 4; jq++) {
            float va[8];
            *(float4*)&va[0] = xr[2 * jq];
            *(float4*)&va[4] = xr[2 * jq + 1];
            uint32_t H[4];
            #pragma unroll
            for (int p2 = 0; p2 < 4; p2++)
                H[p2] = pack_h2(va[2 * p2], va[2 * p2 + 1]);
            uint32_t off = sw128((uint32_t)(row * 128 + (half * 32 + 8 * jq) * 2));
            *(uint4*)(Ah + off) = make_uint4(H[0], H[1], H[2], H[3]);
        }
        // ---- copy B frag table for this chunk ----
        {
            size_t cbase = (size_t)((c0g + ch) * 4) * 288;
            const uint4* srcH = (const uint4*)(g_Bh + cbase);
            uint4* dH = (uint4*)(dyn + s * STAGE_BYTES + ST_B);
            #pragma unroll
            for (int i = 0; i < 3; i++) {
                int idx = t + i * 256;
                if (idx < 576) dH[idx] = srcH[idx];
            }
        }
        // ---- prefetch next chunk's x ----
        if (ch + 1 < nch) {
            const float* xb = xrow + (ch + 1) * 64;
            #pragma unroll
            for (int i = 0; i < 8; i++) xr[i] = *(const float4*)(xb + i * 4);
        }
        __syncthreads();
        // ---- mma over 4 k16 steps ----
        uint32_t ahb = dynb + s * STAGE_BYTES + ST_A;
        const char* bhb = dyn + s * STAGE_BYTES + ST_B;
        #pragma unroll
        for (int s16 = 0; s16 < 4; s16++) {
            uint32_t off = arow_off + s16 * 32;
            uint32_t sw  = off ^ ((off >> 3) & 0x70);
            uint32_t ah[4];
            ldmatrix_x4(ah, ahb + sw);
            int bofs = ((s16 * 9) * 32 + lane) * 8;
            #pragma unroll
            for (int j = 0; j < 9; j++) {
                uint2 bh = *(const uint2*)(bhb + bofs + j * 256);
                mma16816(acc[j], ah, bh.x, bh.y);
            }
        }
        if (ch + 1 < nch) __syncthreads();
    }

    // ---- epilogue: write partials ----
    int r0 = rbase + wid * 16 + (lane >> 2);
    int c0 = 2 * (lane & 3);
    float* dst = g_part + ((size_t)ks * BT + r0) * NPADP + c0;
    #pragma unroll
    for (int j = 0; j < 9; j++) {
        *(float2*)(dst + 8 * j)                      = make_float2(acc[j][0], acc[j][1]);
        *(float2*)(dst + 8 * (size_t)NPADP + 8 * j)  = make_float2(acc[j][2], acc[j][3]);
    }
}

// ---------------- kernel 3: decoder (fused 9-way reduce; 1 warp per frame) ----------------
#define WSZ     720
#define OFF_P   0
#define OFF_HP  72
#define OFF_R   120
#define OFF_ROD 264
#define OFF_J   400
#define OFF_G   448
#define OFF_CT  640
#define OFF_CH  688
#define OFF_MS  704

__global__ void __launch_bounds__(256) decoder_kernel(
        const float* __restrict__ comps,
        const float* __restrict__ meanh,
        const float* __restrict__ bias,
        float* __restrict__ out) {
    __shared__ float cshare[2032];
    __shared__ __align__(16) float sh[8 * WSZ];
    for (int i = threadIdx.x; i < 2025; i += 256) cshare[i] = comps[i];
    __syncthreads();

    int wid  = threadIdx.x >> 5;
    int lane = threadIdx.x & 31;
    int bt   = blockIdx.x * 8 + wid;

    float* S   = sh + wid * WSZ;
    float* p   = S + OFF_P;
    float* hp  = S + OFF_HP;
    float* R   = S + OFF_R;
    float* rod = S + OFF_ROD;
    float* Jj  = S + OFF_J;
    float* G   = S + OFF_G;
    float* CT  = S + OFF_CT;
    float* ch  = S + OFF_CH;
    float* ms  = S + OFF_MS;

    // 1. fused reduce: p = bias + sum of 9 partials; emit theta/beta
    for (int i = lane; i < NOUT; i += 32) {
        float s = bias[i];
        const float* gp = g_part + (size_t)bt * NPADP + i;
        #pragma unroll
        for (int ks = 0; ks < KSPLIT; ks++)
            s += gp[(size_t)ks * BT * NPADP];
        p[i] = s;
        if (i < 48)      out[THETA_OFF + bt * 48 + i] = s;
        else if (i < 58) out[BETA_OFF  + bt * 10 + (i - 48)] = s;
    }
    __syncwarp();

    // 2. full pose
    if (lane < 3) hp[lane] = p[lane];
    for (int i = lane; i < 45; i += 32) {
        float s0 = meanh[i], s1 = 0.0f, s2 = 0.0f;
        #pragma unroll
        for (int j = 0; j < 45; j += 3) {
            s0 += p[3 + j]     * cshare[j * 45 + i];
            s1 += p[3 + j + 1] * cshare[(j + 1) * 45 + i];
            s2 += p[3 + j + 2] * cshare[(j + 2) * 45 + i];
        }
        hp[3 + i] = s0 + s1 + s2;
    }
    __syncwarp();

    // 3. rodrigues
    if (lane < 16) {
        int j = lane;
        float rx = hp[3*j], ry = hp[3*j+1], rz = hp[3*j+2];
        float th = sqrtf(rx*rx + ry*ry + rz*rz + 1e-8f);
        float inv = 1.0f / th;
        float nx = rx*inv, ny = ry*inv, nz = rz*inv;
        float sn, cc;
        __sincosf(th, &sn, &cc);
        float oc = 1.0f - cc;
        float r0 = cc + oc*nx*nx,    r1 = oc*nx*ny - sn*nz, r2 = oc*nx*nz + sn*ny;
        float r3 = oc*nx*ny + sn*nz, r4 = cc + oc*ny*ny,    r5 = oc*ny*nz - sn*nx;
        float r6 = oc*nx*nz - sn*ny, r7 = oc*ny*nz + sn*nx, r8 = cc + oc*nz*nz;
        float* Rj = R + j * 9;
        Rj[0]=r0; Rj[1]=r1; Rj[2]=r2; Rj[3]=r3; Rj[4]=r4; Rj[5]=r5; Rj[6]=r6; Rj[7]=r7; Rj[8]=r8;
        if (j >= 1) {
            float* rd = rod + (j - 1) * 9;
            rd[0]=r0; rd[1]=r1; rd[2]=r2; rd[3]=r3; rd[4]=r4; rd[5]=r5; rd[6]=r6; rd[7]=r7; rd[8]=r8;
        } else {
            rod[135] = 0.0f;
        }
    }
    // 4. joints
    if (lane < 16) {
        int j = lane;
        #pragma unroll
        for (int c = 0; c < 3; c++) {
            float s = g_Jt[j * 3 + c];
            #pragma unroll
            for (int k = 0; k < 10; k++) s += g_Jsh[j * 30 + c * 10 + k] * p[48 + k];
            Jj[j * 3 + c] = s;
        }
    }
    __syncwarp();

    // 5. kinematic chain
    if (lane < 5) {
        float Gp[12];
        #pragma unroll
        for (int r = 0; r < 3; r++) {
            Gp[r*4+0] = R[r*3+0]; Gp[r*4+1] = R[r*3+1]; Gp[r*4+2] = R[r*3+2];
            Gp[r*4+3] = Jj[r];
        }
        if (lane == 0) {
            #pragma unroll
            for (int e = 0; e < 12; e++) G[e] = Gp[e];
        }
        int j = 3 * lane + 1;
        int parent = 0;
        #pragma unroll
        for (int s = 0; s < 3; s++, j++) {
            const float* Rc = R + j * 9;
            float d0 = Jj[j*3+0] - Jj[parent*3+0];
            float d1 = Jj[j*3+1] - Jj[parent*3+1];
            float d2 = Jj[j*3+2] - Jj[parent*3+2];
            float Gc[12];
            #pragma unroll
            for (int r = 0; r < 3; r++) {
                float a0 = Gp[r*4+0], a1 = Gp[r*4+1], a2 = Gp[r*4+2];
                Gc[r*4+0] = a0*Rc[0] + a1*Rc[3] + a2*Rc[6];
                Gc[r*4+1] = a0*Rc[1] + a1*Rc[4] + a2*Rc[7];
                Gc[r*4+2] = a0*Rc[2] + a1*Rc[5] + a2*Rc[8];
                Gc[r*4+3] = a0*d0 + a1*d1 + a2*d2 + Gp[r*4+3];
            }
            #pragma unroll
            for (int e = 0; e < 12; e++) { G[j*12+e] = Gc[e]; Gp[e] = Gc[e]; }
            parent = j;
        }
    }
    __syncwarp();

    // 6. corrected translations
    if (lane < 16) {
        int j = lane;
        #pragma unroll
        for (int r = 0; r < 3; r++) {
            float g0 = G[j*12+r*4+0], g1 = G[j*12+r*4+1], g2 = G[j*12+r*4+2];
            CT[j*3+r] = G[j*12+r*4+3] - (g0*Jj[j*3+0] + g1*Jj[j*3+1] + g2*Jj[j*3+2]);
        }
    }
    __syncwarp();

    // 7. posed positions at 5 mesh vertices
    if (lane < 15) {
        int v = lane / 3, c = lane - 3 * v;
        float s = g_tmpl5[lane];
        #pragma unroll
        for (int k = 0; k < 10; k++) s += g_sd5[v][c][k] * p[48 + k];
        ull a0 = 0ull, a1 = 0ull;
        const ull* pd = (const ull*)g_pd5[v][c];
        const ull* rr = (const ull*)rod;
        #pragma unroll
        for (int i = 0; i < 68; i += 2) {
            ffma2(a0, pd[i],     rr[i]);
            ffma2(a1, pd[i + 1], rr[i + 1]);
        }
        float l0, h0, l1, h1;
        unpack2(a0, l0, h0); unpack2(a1, l1, h1);
        ch[lane] = s + ((l0 + h0) + (l1 + h1));
    }
    __syncwarp();

    // 8. LBS
    if (lane < 15) {
        int v = lane / 3, r = lane - 3 * v;
        float T0 = 0, T1 = 0, T2 = 0, T3a = 0, T3b = 0;
        #pragma unroll
        for (int j = 0; j < 16; j++) {
            float w = g_lbs5[v][j];
            T0 += w * G[j*12+r*4+0];
            T1 += w * G[j*12+r*4+1];
            T2 += w * G[j*12+r*4+2];
            if (j & 1) T3a += w * CT[j*3+r]; else T3b += w * CT[j*3+r];
        }
        ms[lane] = T0 * ch[v*3+0] + T1 * ch[v*3+1] + T2 * ch[v*3+2] + (T3a + T3b);
    }
    __syncwarp();

    // 9. reorder + projection
    if (lane < 21) {
        int m = d_MAP[lane];
        float q0, q1, q2;
        if (m >= 0) { q0 = G[m*12+3]; q1 = G[m*12+7]; q2 = G[m*12+11]; }
        else        { int mi = -m - 1; q0 = ms[mi*3+0]; q1 = ms[mi*3+1]; q2 = ms[mi*3+2]; }
        float csv = p[69];
        #pragma unroll
        for (int col = 0; col < 2; col++) {
            float u = q0 * p[58 + col] + q1 * p[61 + col] + q2 * p[64 + col];
            out[J2D_OFF + (size_t)bt * 42 + lane * 2 + col] = csv * u + p[67 + col];
        }
    }
}

// ---------------- launcher ----------------
extern "C" void kernel_launch(void* const* d_in, const int* in_sizes, int n_in,
                              void* d_out, int out_size) {
    const float* x         = (const float*)d_in[0];
    const float* W         = (const float*)d_in[1];
    const float* b         = (const float*)d_in[2];
    const float* comps     = (const float*)d_in[3];
    const float* meanh     = (const float*)d_in[4];
    const float* tmpl      = (const float*)d_in[5];
    const float* shapedirs = (const float*)d_in[6];
    const float* posedirs  = (const float*)d_in[7];
    const float* Jreg      = (const float*)d_in[8];
    const float* lbs       = (const float*)d_in[9];
    float* out = (float*)d_out;

    cudaFuncSetAttribute(gemm_kernel, cudaFuncAttributeMaxDynamicSharedMemorySize, DYN_SMEM);

    precompute_kernel<<<1292, 128>>>(Jreg, shapedirs, tmpl, posedirs, lbs, W);
    gemm_kernel<<<MTILES * KSPLIT, 256, DYN_SMEM>>>(x);
    decoder_kernel<<<BT / 8, 256>>>(comps, meanh, b, out);
}